// round 1
// baseline (speedup 1.0000x reference)
#include <cuda_runtime.h>
#include <cuda_bf16.h>
#include <cstdint>

// Problem constants
#define NE 8
#define ND 1024
#define NF 4096
#define NT 8192
#define NC 2048

// ---------------- scratch (device globals; no runtime allocation) ----------
__device__ float g_scoresT[NE * NT];            // gates^T  [E, T]
__device__ int   g_idx[NE * NC];                // selected token ids [E, C]
__device__ float g_vals[NE * NC];               // routing probs of selected
__device__ float g_h[(size_t)NE * NC * NF];     // gelu(xg@W1+b1)  [E*C, F]

// ---------------- init output ------------------------------------------------
__global__ void init_out_kernel(float* out, size_t n_main, size_t total) {
    size_t i = (size_t)blockIdx.x * blockDim.x + threadIdx.x;
    size_t stride = (size_t)gridDim.x * blockDim.x;
    for (; i < total; i += stride) {
        if (i < n_main)       out[i] = 0.0f;
        else if (i == n_main) out[i] = 2.0f;   // aux_loss is analytically E*(C/T)*1 = 2
        else                  out[i] = 0.0f;
    }
}

// ---------------- router: gates = softmax(x @ Wg), stored transposed --------
__global__ void router_kernel(const float* __restrict__ x,
                              const float* __restrict__ Wg) {
    int warp = (blockIdx.x * blockDim.x + threadIdx.x) >> 5;
    int lane = threadIdx.x & 31;
    if (warp >= NT) return;
    const float* xr = x + (size_t)warp * ND;
    float acc[NE];
#pragma unroll
    for (int e = 0; e < NE; e++) acc[e] = 0.0f;
    for (int d = lane; d < ND; d += 32) {
        float xv = xr[d];
        const float4 w0 = *(const float4*)(Wg + d * NE);
        const float4 w1 = *(const float4*)(Wg + d * NE + 4);
        acc[0] += xv * w0.x; acc[1] += xv * w0.y;
        acc[2] += xv * w0.z; acc[3] += xv * w0.w;
        acc[4] += xv * w1.x; acc[5] += xv * w1.y;
        acc[6] += xv * w1.z; acc[7] += xv * w1.w;
    }
#pragma unroll
    for (int off = 16; off > 0; off >>= 1) {
#pragma unroll
        for (int e = 0; e < NE; e++)
            acc[e] += __shfl_down_sync(0xffffffffu, acc[e], off);
    }
    if (lane == 0) {
        float m = acc[0];
#pragma unroll
        for (int e = 1; e < NE; e++) m = fmaxf(m, acc[e]);
        float s = 0.0f;
#pragma unroll
        for (int e = 0; e < NE; e++) { acc[e] = expf(acc[e] - m); s += acc[e]; }
        float inv = 1.0f / s;
#pragma unroll
        for (int e = 0; e < NE; e++) g_scoresT[e * NT + warp] = acc[e] * inv;
    }
}

// ---------------- exact top-C per expert via 4-pass radix select ------------
__global__ void topk_kernel() {
    int e = blockIdx.x;
    int tid = threadIdx.x;
    const float* s = g_scoresT + e * NT;

    __shared__ unsigned hist[256];
    __shared__ unsigned sh_prefix;
    __shared__ int sh_rem;

    unsigned prefix = 0;
    int remaining = NC;

    for (int shift = 24; shift >= 0; shift -= 8) {
        if (tid < 256) hist[tid] = 0;
        __syncthreads();
        unsigned mask = (shift == 24) ? 0u : (0xFFFFFFFFu << (shift + 8));
        for (int t = tid; t < NT; t += blockDim.x) {
            unsigned k = __float_as_uint(s[t]);   // all values >= 0 -> monotonic
            if ((k & mask) == prefix) atomicAdd(&hist[(k >> shift) & 0xFFu], 1u);
        }
        __syncthreads();
        if (tid == 0) {
            int rem = remaining;
            int b = 0;
            for (int d = 255; d >= 0; d--) {
                int h = (int)hist[d];
                if (h >= rem) { b = d; break; }
                rem -= h;
            }
            sh_prefix = prefix | ((unsigned)b << shift);
            sh_rem = rem;
        }
        __syncthreads();
        prefix = sh_prefix;
        remaining = sh_rem;
        __syncthreads();
    }

    __shared__ int cnt_gt, cnt_eq;
    if (tid == 0) { cnt_gt = 0; cnt_eq = 0; }
    __syncthreads();
    int base = NC - remaining;   // number of strictly-greater keys (exact)
    for (int t = tid; t < NT; t += blockDim.x) {
        unsigned k = __float_as_uint(s[t]);
        if (k > prefix) {
            int p = atomicAdd(&cnt_gt, 1);
            g_idx[e * NC + p]  = t;
            g_vals[e * NC + p] = s[t];
        } else if (k == prefix) {
            int p = atomicAdd(&cnt_eq, 1);
            if (p < remaining) {
                g_idx[e * NC + base + p]  = t;
                g_vals[e * NC + base + p] = s[t];
            }
        }
    }
}

// ---------------- gelu (tanh approximation, matching jax.nn.gelu default) ---
__device__ __forceinline__ float gelu_f(float v) {
    float u = 0.7978845608028654f * (v + 0.044715f * v * v * v);
    return 0.5f * v * (1.0f + tanhf(u));
}

// ---------------- GEMM1: h = gelu(x[idx] @ W1[e] + b1[e])  ------------------
// M = E*C = 16384, K = D = 1024, N = F = 4096.  128x128x16 tile, 256 threads.
__global__ __launch_bounds__(256) void gemm1_kernel(
    const float* __restrict__ x,
    const float* __restrict__ W1,
    const float* __restrict__ b1) {
    const int BM = 128, BN = 128, BK = 16;
    __shared__ __align__(16) float As[BK][BM];
    __shared__ __align__(16) float Bs[BK][BN];
    __shared__ int rowtok[BM];

    int bn = blockIdx.x, bm = blockIdx.y;
    int m0 = bm * BM, n0 = bn * BN;
    int e = m0 / NC;                // BM divides C -> one expert per block
    int tid = threadIdx.x;
    if (tid < BM) rowtok[tid] = g_idx[m0 + tid];
    __syncthreads();

    int tx = tid & 15, ty = tid >> 4;
    float acc[8][8];
#pragma unroll
    for (int i = 0; i < 8; i++)
#pragma unroll
        for (int j = 0; j < 8; j++) acc[i][j] = 0.0f;

    const float* Bbase = W1 + (size_t)e * ND * NF + n0;

    for (int k0 = 0; k0 < ND; k0 += BK) {
#pragma unroll
        for (int i = 0; i < 2; i++) {
            int t = tid + i * 256;
            // A: 128 rows x 16 cols = 512 float4 (gathered rows)
            int row = t >> 2;
            int kk = (t & 3) << 2;
            float4 v = *(const float4*)(x + (size_t)rowtok[row] * ND + k0 + kk);
            As[kk + 0][row] = v.x; As[kk + 1][row] = v.y;
            As[kk + 2][row] = v.z; As[kk + 3][row] = v.w;
            // B: 16 rows x 128 cols = 512 float4
            int rowb = t >> 5;
            int col = (t & 31) << 2;
            *(float4*)&Bs[rowb][col] =
                *(const float4*)(Bbase + (size_t)(k0 + rowb) * NF + col);
        }
        __syncthreads();
#pragma unroll
        for (int k = 0; k < BK; k++) {
            float4 a0 = *(float4*)&As[k][ty * 8];
            float4 a1 = *(float4*)&As[k][ty * 8 + 4];
            float4 b0 = *(float4*)&Bs[k][tx * 8];
            float4 b1v = *(float4*)&Bs[k][tx * 8 + 4];
            float ar[8] = {a0.x, a0.y, a0.z, a0.w, a1.x, a1.y, a1.z, a1.w};
            float br[8] = {b0.x, b0.y, b0.z, b0.w, b1v.x, b1v.y, b1v.z, b1v.w};
#pragma unroll
            for (int i = 0; i < 8; i++)
#pragma unroll
                for (int j = 0; j < 8; j++)
                    acc[i][j] = fmaf(ar[i], br[j], acc[i][j]);
        }
        __syncthreads();
    }

    const float* b1e = b1 + e * NF + n0 + tx * 8;
#pragma unroll
    for (int i = 0; i < 8; i++) {
        float* hr = g_h + (size_t)(m0 + ty * 8 + i) * NF + n0 + tx * 8;
#pragma unroll
        for (int j = 0; j < 8; j++)
            hr[j] = gelu_f(acc[i][j] + b1e[j]);
    }
}

// ---------------- GEMM2: out[tok] += vals * (h @ W2[e] + b2[e]) -------------
// M = 16384, K = F = 4096, N = D = 1024.
__global__ __launch_bounds__(256) void gemm2_kernel(
    const float* __restrict__ W2,
    const float* __restrict__ b2,
    float* __restrict__ out) {
    const int BM = 128, BN = 128, BK = 16;
    __shared__ __align__(16) float As[BK][BM];
    __shared__ __align__(16) float Bs[BK][BN];
    __shared__ int rowtok[BM];
    __shared__ float rowval[BM];

    int bn = blockIdx.x, bm = blockIdx.y;
    int m0 = bm * BM, n0 = bn * BN;
    int e = m0 / NC;
    int tid = threadIdx.x;
    if (tid < BM) {
        rowtok[tid] = g_idx[m0 + tid];
        rowval[tid] = g_vals[m0 + tid];
    }
    __syncthreads();

    int tx = tid & 15, ty = tid >> 4;
    float acc[8][8];
#pragma unroll
    for (int i = 0; i < 8; i++)
#pragma unroll
        for (int j = 0; j < 8; j++) acc[i][j] = 0.0f;

    const float* Bbase = W2 + (size_t)e * NF * ND + n0;

    for (int k0 = 0; k0 < NF; k0 += BK) {
#pragma unroll
        for (int i = 0; i < 2; i++) {
            int t = tid + i * 256;
            int row = t >> 2;
            int kk = (t & 3) << 2;
            float4 v = *(const float4*)(g_h + (size_t)(m0 + row) * NF + k0 + kk);
            As[kk + 0][row] = v.x; As[kk + 1][row] = v.y;
            As[kk + 2][row] = v.z; As[kk + 3][row] = v.w;
            int rowb = t >> 5;
            int col = (t & 31) << 2;
            *(float4*)&Bs[rowb][col] =
                *(const float4*)(Bbase + (size_t)(k0 + rowb) * ND + col);
        }
        __syncthreads();
#pragma unroll
        for (int k = 0; k < BK; k++) {
            float4 a0 = *(float4*)&As[k][ty * 8];
            float4 a1 = *(float4*)&As[k][ty * 8 + 4];
            float4 b0 = *(float4*)&Bs[k][tx * 8];
            float4 b1v = *(float4*)&Bs[k][tx * 8 + 4];
            float ar[8] = {a0.x, a0.y, a0.z, a0.w, a1.x, a1.y, a1.z, a1.w};
            float br[8] = {b0.x, b0.y, b0.z, b0.w, b1v.x, b1v.y, b1v.z, b1v.w};
#pragma unroll
            for (int i = 0; i < 8; i++)
#pragma unroll
                for (int j = 0; j < 8; j++)
                    acc[i][j] = fmaf(ar[i], br[j], acc[i][j]);
        }
        __syncthreads();
    }

    const float* b2e = b2 + e * ND + n0 + tx * 8;
#pragma unroll
    for (int i = 0; i < 8; i++) {
        int m = ty * 8 + i;
        int tok = rowtok[m];
        float w = rowval[m];
        float* orow = out + (size_t)tok * ND + n0 + tx * 8;
#pragma unroll
        for (int j = 0; j < 8; j++) {
            float v = (acc[i][j] + b2e[j]) * w;
            atomicAdd(&orow[j], v);
        }
    }
}

// ---------------- launch -----------------------------------------------------
extern "C" void kernel_launch(void* const* d_in, const int* in_sizes, int n_in,
                              void* d_out, int out_size) {
    const float* x  = (const float*)d_in[0];   // [T, D]
    const float* Wg = (const float*)d_in[1];   // [D, E]
    const float* W1 = (const float*)d_in[2];   // [E, D, F]
    const float* b1 = (const float*)d_in[3];   // [E, F]
    const float* W2 = (const float*)d_in[4];   // [E, F, D]
    const float* b2 = (const float*)d_in[5];   // [E, D]
    float* out = (float*)d_out;

    size_t n_main = (size_t)NT * ND;
    init_out_kernel<<<512, 256>>>(out, n_main, (size_t)out_size);
    router_kernel<<<NT / 32, 1024>>>(x, Wg);          // 32 warps/block, 1 token/warp
    topk_kernel<<<NE, 1024>>>();
    gemm1_kernel<<<dim3(NF / 128, (NE * NC) / 128), 256>>>(x, W1, b1);
    gemm2_kernel<<<dim3(ND / 128, (NE * NC) / 128), 256>>>(W2, b2, out);
}

// round 4
// speedup vs baseline: 1.4404x; 1.4404x over previous
#include <cuda_runtime.h>
#include <cstdint>

// Problem constants
#define NE 8
#define ND 1024
#define NF 4096
#define NT 8192
#define NC 2048
#define NM (NE * NC)   // 16384 rows through the expert FFN

// ---------------- scratch (device globals; no runtime allocation) ----------
__device__ float g_scoresT[NE * NT];              // gates^T  [E, T]
__device__ int   g_idx[NM];                       // selected token ids [E*C]
__device__ float g_vals[NM];                      // routing probs of selected
__device__ float g_h[(size_t)NM * NF];            // gelu(xg@W1+b1)  [E*C, F]

// ---------------- init output ------------------------------------------------
__global__ void init_out_kernel(float* out, size_t n_main, size_t total) {
    size_t i = (size_t)blockIdx.x * blockDim.x + threadIdx.x;
    size_t stride = (size_t)gridDim.x * blockDim.x;
    for (; i < total; i += stride) {
        if (i < n_main)       out[i] = 0.0f;
        else if (i == n_main) out[i] = 2.0f;   // aux_loss = E*(C/T)*1 = 2 analytically
        else                  out[i] = 0.0f;
    }
}

// ---------------- router: gates = softmax(x @ Wg), stored transposed --------
__global__ void router_kernel(const float* __restrict__ x,
                              const float* __restrict__ Wg) {
    int warp = (blockIdx.x * blockDim.x + threadIdx.x) >> 5;
    int lane = threadIdx.x & 31;
    if (warp >= NT) return;
    const float* xr = x + (size_t)warp * ND;
    float acc[NE];
#pragma unroll
    for (int e = 0; e < NE; e++) acc[e] = 0.0f;
    for (int d = lane; d < ND; d += 32) {
        float xv = xr[d];
        const float4 w0 = *(const float4*)(Wg + d * NE);
        const float4 w1 = *(const float4*)(Wg + d * NE + 4);
        acc[0] += xv * w0.x; acc[1] += xv * w0.y;
        acc[2] += xv * w0.z; acc[3] += xv * w0.w;
        acc[4] += xv * w1.x; acc[5] += xv * w1.y;
        acc[6] += xv * w1.z; acc[7] += xv * w1.w;
    }
#pragma unroll
    for (int off = 16; off > 0; off >>= 1) {
#pragma unroll
        for (int e = 0; e < NE; e++)
            acc[e] += __shfl_down_sync(0xffffffffu, acc[e], off);
    }
    if (lane == 0) {
        float m = acc[0];
#pragma unroll
        for (int e = 1; e < NE; e++) m = fmaxf(m, acc[e]);
        float s = 0.0f;
#pragma unroll
        for (int e = 0; e < NE; e++) { acc[e] = expf(acc[e] - m); s += acc[e]; }
        float inv = 1.0f / s;
#pragma unroll
        for (int e = 0; e < NE; e++) g_scoresT[e * NT + warp] = acc[e] * inv;
    }
}

// ---------------- exact top-C per expert via 4-pass radix select ------------
__global__ void topk_kernel() {
    int e = blockIdx.x;
    int tid = threadIdx.x;
    const float* s = g_scoresT + e * NT;

    __shared__ unsigned hist[256];
    __shared__ unsigned sh_prefix;
    __shared__ int sh_rem;

    unsigned prefix = 0;
    int remaining = NC;

    for (int shift = 24; shift >= 0; shift -= 8) {
        if (tid < 256) hist[tid] = 0;
        __syncthreads();
        unsigned mask = (shift == 24) ? 0u : (0xFFFFFFFFu << (shift + 8));
        for (int t = tid; t < NT; t += blockDim.x) {
            unsigned k = __float_as_uint(s[t]);
            if ((k & mask) == prefix) atomicAdd(&hist[(k >> shift) & 0xFFu], 1u);
        }
        __syncthreads();
        if (tid == 0) {
            int rem = remaining;
            int b = 0;
            for (int d = 255; d >= 0; d--) {
                int h = (int)hist[d];
                if (h >= rem) { b = d; break; }
                rem -= h;
            }
            sh_prefix = prefix | ((unsigned)b << shift);
            sh_rem = rem;
        }
        __syncthreads();
        prefix = sh_prefix;
        remaining = sh_rem;
        __syncthreads();
    }

    __shared__ int cnt_gt, cnt_eq;
    if (tid == 0) { cnt_gt = 0; cnt_eq = 0; }
    __syncthreads();
    int base = NC - remaining;
    for (int t = tid; t < NT; t += blockDim.x) {
        unsigned k = __float_as_uint(s[t]);
        if (k > prefix) {
            int p = atomicAdd(&cnt_gt, 1);
            g_idx[e * NC + p]  = t;
            g_vals[e * NC + p] = s[t];
        } else if (k == prefix) {
            int p = atomicAdd(&cnt_eq, 1);
            if (p < remaining) {
                g_idx[e * NC + base + p]  = t;
                g_vals[e * NC + base + p] = s[t];
            }
        }
    }
}

// ---------------- gelu (tanh approximation, matches jax.nn.gelu) ------------
__device__ __forceinline__ float gelu_f(float v) {
    float u = 0.7978845608028654f * (v + 0.044715f * v * v * v);
    return 0.5f * v * (1.0f + tanhf(u));
}

// ============================ 3xTF32 mma.sync GEMM ============================
// CTA tile 128(M) x 256(N) x 32(K). 8 warps in 2(m) x 4(n), warp tile 64x64.
// Each fp32 operand split v = hi + lo (both exact in tf32); accumulate
// hi*hi + hi*lo + lo*hi -> fp32-level accuracy on tensor cores.

static constexpr int AS_STRIDE = 36;
static constexpr int BS_STRIDE = 264;
static constexpr int AS_FLOATS = 128 * AS_STRIDE;    // 4608
static constexpr int BS_FLOATS = 32 * BS_STRIDE;     // 8448
static constexpr int GEMM_SMEM_BYTES = (2 * AS_FLOATS + 2 * BS_FLOATS) * 4;  // 104448

__device__ __forceinline__ uint32_t smem_u32(const void* p) {
    uint32_t a;
    asm("{ .reg .u64 t; cvta.to.shared.u64 t, %1; cvt.u32.u64 %0, t; }"
        : "=r"(a) : "l"(p));
    return a;
}

__device__ __forceinline__ void cp16(uint32_t dst, const void* src) {
    asm volatile("cp.async.cg.shared.global [%0], [%1], 16;"
                 :: "r"(dst), "l"(src) : "memory");
}
#define CP_COMMIT() asm volatile("cp.async.commit_group;" ::: "memory")
#define CP_WAIT1()  asm volatile("cp.async.wait_group 1;" ::: "memory")

__device__ __forceinline__ void mma_tf32(float* d, const uint32_t* a,
                                         const uint32_t* b) {
    asm volatile(
        "mma.sync.aligned.m16n8k8.row.col.f32.tf32.tf32.f32 "
        "{%0,%1,%2,%3}, {%4,%5,%6,%7}, {%8,%9}, {%0,%1,%2,%3};"
        : "+f"(d[0]), "+f"(d[1]), "+f"(d[2]), "+f"(d[3])
        : "r"(a[0]), "r"(a[1]), "r"(a[2]), "r"(a[3]), "r"(b[0]), "r"(b[1]));
}

__device__ __forceinline__ void split_tf32(float v, uint32_t& hi, uint32_t& lo) {
    uint32_t h;
    asm("cvt.rna.tf32.f32 %0, %1;" : "=r"(h) : "f"(v));
    float lf = v - __uint_as_float(h);
    uint32_t l;
    asm("cvt.rna.tf32.f32 %0, %1;" : "=r"(l) : "f"(lf));
    hi = h; lo = l;
}

__device__ __forceinline__ void red_v2(float* ptr, float v0, float v1) {
    asm volatile("red.global.add.v2.f32 [%0], {%1, %2};"
                 :: "l"(ptr), "f"(v0), "f"(v1) : "memory");
}

// K = NCH*32. GATHER: A rows come from g_idx tokens (row stride ND).
// GELU_EPI: write gelu(acc+bias) to outp rows; else scatter-add (acc+bias)*val.
template<int NCH, bool GATHER, bool GELU_EPI>
__global__ __launch_bounds__(256) void gemm_tc_kernel(
    const float* __restrict__ A,
    const float* __restrict__ B,
    const float* __restrict__ bias,
    float* __restrict__ outp,
    int Nld) {
    constexpr int K = NCH * 32;
    extern __shared__ __align__(16) float sm[];
    __shared__ int   tok_s[128];
    __shared__ float val_s[128];

    const int tid = threadIdx.x;
    const int warp = tid >> 5;
    const int lane = tid & 31;
    const int wm = warp >> 2;          // 0..1
    const int wn = warp & 3;           // 0..3
    const int r = lane >> 2;           // 0..7
    const int c = lane & 3;            // 0..3

    const int n0 = blockIdx.x * 256;
    const int m0 = blockIdx.y * 128;
    const int e = m0 >> 11;            // m0 / NC

    if (tid < 128) {
        tok_s[tid] = g_idx[m0 + tid];
        val_s[tid] = g_vals[m0 + tid];
    }
    __syncthreads();

    const float* Bexp = B + (size_t)e * K * Nld + n0;
    const uint32_t sbase = smem_u32(sm);

    auto load_stage = [&](int s, int kc) {
#pragma unroll
        for (int i = 0; i < 4; i++) {                  // A: 128x32 = 1024 f4
            int lin = tid + 256 * i;
            int row = lin >> 3;
            int c4 = (lin & 7) * 4;
            const float* src = GATHER
                ? (A + (size_t)tok_s[row] * ND + kc + c4)
                : (A + (size_t)(m0 + row) * K + kc + c4);
            cp16(sbase + (uint32_t)(s * AS_FLOATS + row * AS_STRIDE + c4) * 4, src);
        }
#pragma unroll
        for (int i = 0; i < 8; i++) {                  // B: 32x256 = 2048 f4
            int lin = tid + 256 * i;
            int row = lin >> 6;
            int c4 = (lin & 63) * 4;
            const float* src = Bexp + (size_t)(kc + row) * Nld + c4;
            cp16(sbase + (uint32_t)(2 * AS_FLOATS + s * BS_FLOATS +
                                    row * BS_STRIDE + c4) * 4, src);
        }
    };

    float acc[4][8][4];
#pragma unroll
    for (int mt = 0; mt < 4; mt++)
#pragma unroll
        for (int nt = 0; nt < 8; nt++)
#pragma unroll
            for (int i = 0; i < 4; i++) acc[mt][nt][i] = 0.0f;

    // prologue: fill both stages
    load_stage(0, 0);
    CP_COMMIT();
    load_stage(1, 32);
    CP_COMMIT();

#pragma unroll 1
    for (int ch = 0; ch < NCH; ch++) {
        const int s = ch & 1;
        CP_WAIT1();
        __syncthreads();

        const float* As = sm + s * AS_FLOATS;
        const float* Bs = sm + 2 * AS_FLOATS + s * BS_FLOATS;
#pragma unroll
        for (int ks = 0; ks < 4; ks++) {
            const int kb = ks * 8;
            uint32_t afh[4][4], afl[4][4];
#pragma unroll
            for (int mt = 0; mt < 4; mt++) {
                int m = wm * 64 + mt * 16;
                split_tf32(As[(m + r)     * AS_STRIDE + kb + c],     afh[mt][0], afl[mt][0]);
                split_tf32(As[(m + r + 8) * AS_STRIDE + kb + c],     afh[mt][1], afl[mt][1]);
                split_tf32(As[(m + r)     * AS_STRIDE + kb + c + 4], afh[mt][2], afl[mt][2]);
                split_tf32(As[(m + r + 8) * AS_STRIDE + kb + c + 4], afh[mt][3], afl[mt][3]);
            }
#pragma unroll
            for (int nt = 0; nt < 8; nt++) {
                int n = wn * 64 + nt * 8;
                uint32_t bh[2], bl[2];
                split_tf32(Bs[(kb + c)     * BS_STRIDE + n + r], bh[0], bl[0]);
                split_tf32(Bs[(kb + c + 4) * BS_STRIDE + n + r], bh[1], bl[1]);
#pragma unroll
                for (int mt = 0; mt < 4; mt++) {
                    mma_tf32(acc[mt][nt], afh[mt], bh);   // hi*hi
                    mma_tf32(acc[mt][nt], afl[mt], bh);   // lo*hi
                    mma_tf32(acc[mt][nt], afh[mt], bl);   // hi*lo
                }
            }
        }
        __syncthreads();
        if (ch + 2 < NCH) load_stage(s, (ch + 2) * 32);
        CP_COMMIT();   // unconditional: keeps wait_group bookkeeping exact
    }

    // ---------------- epilogue -----------------------------------------------
#pragma unroll
    for (int mt = 0; mt < 4; mt++) {
        const int lm0 = wm * 64 + mt * 16 + r;       // local row of acc[0],acc[1]
        const int lm1 = lm0 + 8;                     // local row of acc[2],acc[3]
#pragma unroll
        for (int nt = 0; nt < 8; nt++) {
            const int bcol = n0 + wn * 64 + nt * 8 + c * 2;
            const float bb0 = bias[e * Nld + bcol];
            const float bb1 = bias[e * Nld + bcol + 1];
            if (GELU_EPI) {
                float2 v0 = make_float2(gelu_f(acc[mt][nt][0] + bb0),
                                        gelu_f(acc[mt][nt][1] + bb1));
                float2 v1 = make_float2(gelu_f(acc[mt][nt][2] + bb0),
                                        gelu_f(acc[mt][nt][3] + bb1));
                *(float2*)(outp + (size_t)(m0 + lm0) * Nld + bcol) = v0;
                *(float2*)(outp + (size_t)(m0 + lm1) * Nld + bcol) = v1;
            } else {
                const float w0 = val_s[lm0];
                const float w1 = val_s[lm1];
                float* p0 = outp + (size_t)tok_s[lm0] * ND + bcol;
                float* p1 = outp + (size_t)tok_s[lm1] * ND + bcol;
                red_v2(p0, (acc[mt][nt][0] + bb0) * w0, (acc[mt][nt][1] + bb1) * w0);
                red_v2(p1, (acc[mt][nt][2] + bb0) * w1, (acc[mt][nt][3] + bb1) * w1);
            }
        }
    }
}

// ============================ host launch =====================================
extern "C" void kernel_launch(void* const* d_in, const int* in_sizes, int n_in,
                              void* d_out, int out_size) {
    const float* x  = (const float*)d_in[0];   // [T, D]
    const float* Wg = (const float*)d_in[1];   // [D, E]
    const float* W1 = (const float*)d_in[2];   // [E, D, F]
    const float* b1 = (const float*)d_in[3];   // [E, F]
    const float* W2 = (const float*)d_in[4];   // [E, F, D]
    const float* b2 = (const float*)d_in[5];   // [E, D]
    float* out = (float*)d_out;

    void* p_h;
    cudaGetSymbolAddress(&p_h, g_h);

    cudaFuncSetAttribute((const void*)gemm_tc_kernel<32, true, true>,
                         cudaFuncAttributeMaxDynamicSharedMemorySize,
                         GEMM_SMEM_BYTES);
    cudaFuncSetAttribute((const void*)gemm_tc_kernel<128, false, false>,
                         cudaFuncAttributeMaxDynamicSharedMemorySize,
                         GEMM_SMEM_BYTES);

    size_t n_main = (size_t)NT * ND;
    init_out_kernel<<<512, 256>>>(out, n_main, (size_t)out_size);
    router_kernel<<<NT / 32, 1024>>>(x, Wg);
    topk_kernel<<<NE, 1024>>>();

    // GEMM1: h = gelu(x[idx] @ W1[e] + b1[e])   M=16384, N=4096, K=1024
    gemm_tc_kernel<32, true, true>
        <<<dim3(NF / 256, NM / 128), 256, GEMM_SMEM_BYTES>>>(
            x, W1, b1, (float*)p_h, NF);

    // GEMM2: out[tok] += val * (h @ W2[e] + b2[e])   M=16384, N=1024, K=4096
    gemm_tc_kernel<128, false, false>
        <<<dim3(ND / 256, NM / 128), 256, GEMM_SMEM_BYTES>>>(
            (const float*)p_h, W2, b2, out, ND);
}

// round 5
// speedup vs baseline: 2.5373x; 1.7616x over previous
#include <cuda_runtime.h>
#include <cuda_bf16.h>
#include <cstdint>

// Problem constants
#define NE 8
#define ND 1024
#define NF 4096
#define NT 8192
#define NC 2048
#define NM (NE * NC)   // 16384 rows through the expert FFN

// ---------------- scratch (device globals; no runtime allocation) ----------
__device__ float g_scoresT[NE * NT];              // gates^T  [E, T]
__device__ int   g_idx[NM];                       // selected token ids [E*C]
__device__ float g_vals[NM];                      // routing probs of selected
__device__ __nv_bfloat16 g_xh[(size_t)NT * ND];   // x split hi
__device__ __nv_bfloat16 g_xl[(size_t)NT * ND];   // x split lo
__device__ __nv_bfloat16 g_w1h[(size_t)NE * ND * NF];
__device__ __nv_bfloat16 g_w1l[(size_t)NE * ND * NF];
__device__ __nv_bfloat16 g_w2h[(size_t)NE * NF * ND];
__device__ __nv_bfloat16 g_w2l[(size_t)NE * NF * ND];
__device__ __nv_bfloat16 g_hh[(size_t)NM * NF];   // gelu output split hi
__device__ __nv_bfloat16 g_hl[(size_t)NM * NF];   // gelu output split lo

// ---------------- init output ------------------------------------------------
__global__ void init_out_kernel(float* out, size_t n_main, size_t total) {
    size_t i = (size_t)blockIdx.x * blockDim.x + threadIdx.x;
    size_t stride = (size_t)gridDim.x * blockDim.x;
    for (; i < total; i += stride) {
        if (i < n_main)       out[i] = 0.0f;
        else if (i == n_main) out[i] = 2.0f;   // aux_loss = E*(C/T)*1 = 2 analytically
        else                  out[i] = 0.0f;
    }
}

// ---------------- fp32 -> (hi, lo) bf16 split --------------------------------
__global__ void split_kernel(const float4* __restrict__ in,
                             __nv_bfloat162* __restrict__ hi,
                             __nv_bfloat162* __restrict__ lo, size_t n4) {
    size_t i = (size_t)blockIdx.x * blockDim.x + threadIdx.x;
    size_t stride = (size_t)gridDim.x * blockDim.x;
    for (; i < n4; i += stride) {
        float4 v = in[i];
        __nv_bfloat162 h01, h23, l01, l23;
        h01.x = __float2bfloat16_rn(v.x);
        h01.y = __float2bfloat16_rn(v.y);
        h23.x = __float2bfloat16_rn(v.z);
        h23.y = __float2bfloat16_rn(v.w);
        l01.x = __float2bfloat16_rn(v.x - __bfloat162float(h01.x));
        l01.y = __float2bfloat16_rn(v.y - __bfloat162float(h01.y));
        l23.x = __float2bfloat16_rn(v.z - __bfloat162float(h23.x));
        l23.y = __float2bfloat16_rn(v.w - __bfloat162float(h23.y));
        hi[2 * i] = h01; hi[2 * i + 1] = h23;
        lo[2 * i] = l01; lo[2 * i + 1] = l23;
    }
}

// ---------------- router: gates = softmax(x @ Wg), stored transposed --------
__global__ void router_kernel(const float* __restrict__ x,
                              const float* __restrict__ Wg) {
    int warp = (blockIdx.x * blockDim.x + threadIdx.x) >> 5;
    int lane = threadIdx.x & 31;
    if (warp >= NT) return;
    const float* xr = x + (size_t)warp * ND;
    float acc[NE];
#pragma unroll
    for (int e = 0; e < NE; e++) acc[e] = 0.0f;
    for (int d = lane; d < ND; d += 32) {
        float xv = xr[d];
        const float4 w0 = *(const float4*)(Wg + d * NE);
        const float4 w1 = *(const float4*)(Wg + d * NE + 4);
        acc[0] += xv * w0.x; acc[1] += xv * w0.y;
        acc[2] += xv * w0.z; acc[3] += xv * w0.w;
        acc[4] += xv * w1.x; acc[5] += xv * w1.y;
        acc[6] += xv * w1.z; acc[7] += xv * w1.w;
    }
#pragma unroll
    for (int off = 16; off > 0; off >>= 1) {
#pragma unroll
        for (int e = 0; e < NE; e++)
            acc[e] += __shfl_down_sync(0xffffffffu, acc[e], off);
    }
    if (lane == 0) {
        float m = acc[0];
#pragma unroll
        for (int e = 1; e < NE; e++) m = fmaxf(m, acc[e]);
        float s = 0.0f;
#pragma unroll
        for (int e = 0; e < NE; e++) { acc[e] = expf(acc[e] - m); s += acc[e]; }
        float inv = 1.0f / s;
#pragma unroll
        for (int e = 0; e < NE; e++) g_scoresT[e * NT + warp] = acc[e] * inv;
    }
}

// ---------------- exact top-C per expert via 4-pass radix select ------------
__global__ void topk_kernel() {
    int e = blockIdx.x;
    int tid = threadIdx.x;
    const float* s = g_scoresT + e * NT;

    __shared__ unsigned hist[256];
    __shared__ unsigned sh_prefix;
    __shared__ int sh_rem;

    unsigned prefix = 0;
    int remaining = NC;

    for (int shift = 24; shift >= 0; shift -= 8) {
        if (tid < 256) hist[tid] = 0;
        __syncthreads();
        unsigned mask = (shift == 24) ? 0u : (0xFFFFFFFFu << (shift + 8));
        for (int t = tid; t < NT; t += blockDim.x) {
            unsigned k = __float_as_uint(s[t]);
            if ((k & mask) == prefix) atomicAdd(&hist[(k >> shift) & 0xFFu], 1u);
        }
        __syncthreads();
        if (tid == 0) {
            int rem = remaining;
            int b = 0;
            for (int d = 255; d >= 0; d--) {
                int h = (int)hist[d];
                if (h >= rem) { b = d; break; }
                rem -= h;
            }
            sh_prefix = prefix | ((unsigned)b << shift);
            sh_rem = rem;
        }
        __syncthreads();
        prefix = sh_prefix;
        remaining = sh_rem;
        __syncthreads();
    }

    __shared__ int cnt_gt, cnt_eq;
    if (tid == 0) { cnt_gt = 0; cnt_eq = 0; }
    __syncthreads();
    int base = NC - remaining;
    for (int t = tid; t < NT; t += blockDim.x) {
        unsigned k = __float_as_uint(s[t]);
        if (k > prefix) {
            int p = atomicAdd(&cnt_gt, 1);
            g_idx[e * NC + p]  = t;
            g_vals[e * NC + p] = s[t];
        } else if (k == prefix) {
            int p = atomicAdd(&cnt_eq, 1);
            if (p < remaining) {
                g_idx[e * NC + base + p]  = t;
                g_vals[e * NC + base + p] = s[t];
            }
        }
    }
}

// ---------------- gelu (tanh approximation, matches jax.nn.gelu) ------------
__device__ __forceinline__ float gelu_f(float v) {
    float u = 0.7978845608028654f * (v + 0.044715f * v * v * v);
    return 0.5f * v * (1.0f + tanhf(u));
}

// ============================ 3xBF16 mma.sync GEMM ============================
// CTA tile 128(M) x 256(N) x 32(K). 8 warps in 2(m) x 4(n), warp tile 64x64.
// Operands pre-split into bf16 (hi, lo) planes in GMEM. Accumulate
// hi*hi + lo*hi + hi*lo on mma.m16n8k16.bf16 with fp32 accumulators.
// Fragments via ldmatrix (A) / ldmatrix.trans (B); padded strides -> no
// bank conflicts (A stride 80B: banks 20r%32 distinct; B 528B: 4r%32 distinct).

static constexpr int A_STRIDE = 40;                 // bf16 units (80 B)
static constexpr int A_PLANE  = 128 * A_STRIDE;     // 5120
static constexpr int A_STAGE  = 2 * A_PLANE;        // hi + lo
static constexpr int B_BASE   = 2 * A_STAGE;        // after 2 A stages
static constexpr int B_STRIDE = 264;                // bf16 units (528 B)
static constexpr int B_PLANE  = 32 * B_STRIDE;      // 8448
static constexpr int B_STAGE  = 2 * B_PLANE;
static constexpr int SMEM_BF16 = B_BASE + 2 * B_STAGE;       // 54272
static constexpr int GEMM_SMEM_BYTES = SMEM_BF16 * 2;        // 108544

__device__ __forceinline__ uint32_t smem_u32(const void* p) {
    uint32_t a;
    asm("{ .reg .u64 t; cvta.to.shared.u64 t, %1; cvt.u32.u64 %0, t; }"
        : "=r"(a) : "l"(p));
    return a;
}

__device__ __forceinline__ void cp16(uint32_t dst, const void* src) {
    asm volatile("cp.async.cg.shared.global [%0], [%1], 16;"
                 :: "r"(dst), "l"(src) : "memory");
}
#define CP_COMMIT() asm volatile("cp.async.commit_group;" ::: "memory")
#define CP_WAIT1()  asm volatile("cp.async.wait_group 1;" ::: "memory")

__device__ __forceinline__ void ldsm4(uint32_t* r, uint32_t addr) {
    asm volatile("ldmatrix.sync.aligned.m8n8.x4.shared.b16 {%0,%1,%2,%3}, [%4];"
                 : "=r"(r[0]), "=r"(r[1]), "=r"(r[2]), "=r"(r[3]) : "r"(addr));
}
__device__ __forceinline__ void ldsm4t(uint32_t* r, uint32_t addr) {
    asm volatile("ldmatrix.sync.aligned.m8n8.x4.trans.shared.b16 {%0,%1,%2,%3}, [%4];"
                 : "=r"(r[0]), "=r"(r[1]), "=r"(r[2]), "=r"(r[3]) : "r"(addr));
}

__device__ __forceinline__ void mma_bf16(float* d, const uint32_t* a,
                                         const uint32_t* b) {
    asm volatile(
        "mma.sync.aligned.m16n8k16.row.col.f32.bf16.bf16.f32 "
        "{%0,%1,%2,%3}, {%4,%5,%6,%7}, {%8,%9}, {%0,%1,%2,%3};"
        : "+f"(d[0]), "+f"(d[1]), "+f"(d[2]), "+f"(d[3])
        : "r"(a[0]), "r"(a[1]), "r"(a[2]), "r"(a[3]), "r"(b[0]), "r"(b[1]));
}

__device__ __forceinline__ void red_v2(float* ptr, float v0, float v1) {
    asm volatile("red.global.add.v2.f32 [%0], {%1, %2};"
                 :: "l"(ptr), "f"(v0), "f"(v1) : "memory");
}

// K = NCH*32. GATHER: A rows come from g_idx tokens (row stride ND).
// GELU_EPI: write split-bf16 gelu(acc+bias) to (outbh, outbl) rows;
// else scatter-add (acc+bias)*val into fp32 outa.
template<int NCH, bool GATHER, bool GELU_EPI>
__global__ __launch_bounds__(256) void gemm_tc_kernel(
    const __nv_bfloat16* __restrict__ Ah,
    const __nv_bfloat16* __restrict__ Al,
    const __nv_bfloat16* __restrict__ Bh,
    const __nv_bfloat16* __restrict__ Bl,
    const float* __restrict__ bias,
    float* __restrict__ outa,
    __nv_bfloat16* __restrict__ outbh,
    __nv_bfloat16* __restrict__ outbl,
    int Nld) {
    constexpr int K = NCH * 32;
    extern __shared__ __align__(16) __nv_bfloat16 sm[];
    __shared__ int   tok_s[128];
    __shared__ float val_s[128];

    const int tid = threadIdx.x;
    const int warp = tid >> 5;
    const int lane = tid & 31;
    const int wm = warp >> 2;          // 0..1
    const int wn = warp & 3;           // 0..3
    const int r = lane >> 2;           // 0..7 (accumulator row)
    const int c = lane & 3;            // 0..3 (accumulator col pair)
    const int quad = lane >> 3;        // 0..3 (ldmatrix matrix id)
    const int r8 = lane & 7;           // row within 8x8 matrix

    const int n0 = blockIdx.x * 256;
    const int m0 = blockIdx.y * 128;
    const int e = m0 >> 11;            // m0 / NC

    if (tid < 128) {
        tok_s[tid] = g_idx[m0 + tid];
        val_s[tid] = g_vals[m0 + tid];
    }
    __syncthreads();

    const size_t bexp = (size_t)e * K * Nld + n0;
    const uint32_t sbase = smem_u32(sm);

    auto load_stage = [&](int s, int kc) {
        const __nv_bfloat16* aps[2] = {Ah, Al};
        const __nv_bfloat16* bps[2] = {Bh + bexp, Bl + bexp};
#pragma unroll
        for (int p = 0; p < 2; p++) {
#pragma unroll
            for (int i = 0; i < 2; i++) {              // A: 128 rows x 4 segs
                int lin = tid + 256 * i;
                int row = lin >> 2;
                int seg = (lin & 3) * 8;
                const __nv_bfloat16* src = GATHER
                    ? (aps[p] + (size_t)tok_s[row] * ND + kc + seg)
                    : (aps[p] + (size_t)(m0 + row) * K + kc + seg);
                cp16(sbase + (uint32_t)(s * A_STAGE + p * A_PLANE +
                                        row * A_STRIDE + seg) * 2, src);
            }
#pragma unroll
            for (int i = 0; i < 4; i++) {              // B: 32 rows x 32 segs
                int lin = tid + 256 * i;
                int row = lin >> 5;
                int seg = (lin & 31) * 8;
                const __nv_bfloat16* src = bps[p] + (size_t)(kc + row) * Nld + seg;
                cp16(sbase + (uint32_t)(B_BASE + s * B_STAGE + p * B_PLANE +
                                        row * B_STRIDE + seg) * 2, src);
            }
        }
    };

    float acc[4][8][4];
#pragma unroll
    for (int mt = 0; mt < 4; mt++)
#pragma unroll
        for (int nt = 0; nt < 8; nt++)
#pragma unroll
            for (int i = 0; i < 4; i++) acc[mt][nt][i] = 0.0f;

    // prologue: fill both stages
    load_stage(0, 0);
    CP_COMMIT();
    load_stage(1, 32);
    CP_COMMIT();

#pragma unroll 1
    for (int ch = 0; ch < NCH; ch++) {
        const int s = ch & 1;
        CP_WAIT1();
        __syncthreads();

#pragma unroll
        for (int ks = 0; ks < 2; ks++) {
            // ---- A fragments: hi/lo x 4 m-tiles via ldmatrix.x4 ----
            uint32_t ah[4][4], al[4][4];
            {
                const int m_local = wm * 64 + (quad & 1) * 8 + r8;
                const int k_off = ks * 16 + (quad >> 1) * 8;
                const uint32_t abase = sbase +
                    (uint32_t)(s * A_STAGE + m_local * A_STRIDE + k_off) * 2;
#pragma unroll
                for (int mt = 0; mt < 4; mt++) {
                    ldsm4(ah[mt], abase + (uint32_t)(mt * 16 * A_STRIDE) * 2);
                    ldsm4(al[mt], abase + (uint32_t)(A_PLANE + mt * 16 * A_STRIDE) * 2);
                }
            }
            // ---- B fragments per 16-col group, then MMAs ----
            {
                const int k_row = ks * 16 + (quad & 1) * 8 + r8;
                const int n_col = wn * 64 + (quad >> 1) * 8;
                const uint32_t bbase = sbase +
                    (uint32_t)(B_BASE + s * B_STAGE + k_row * B_STRIDE + n_col) * 2;
#pragma unroll
                for (int nt2 = 0; nt2 < 4; nt2++) {
                    uint32_t bh[4], bl[4];
                    ldsm4t(bh, bbase + (uint32_t)(nt2 * 16) * 2);
                    ldsm4t(bl, bbase + (uint32_t)(B_PLANE + nt2 * 16) * 2);
                    const int nt = nt2 * 2;
#pragma unroll
                    for (int mt = 0; mt < 4; mt++) {
                        mma_bf16(acc[mt][nt],     ah[mt], bh);        // hi*hi
                        mma_bf16(acc[mt][nt],     al[mt], bh);        // lo*hi
                        mma_bf16(acc[mt][nt],     ah[mt], bl);        // hi*lo
                        mma_bf16(acc[mt][nt + 1], ah[mt], bh + 2);
                        mma_bf16(acc[mt][nt + 1], al[mt], bh + 2);
                        mma_bf16(acc[mt][nt + 1], ah[mt], bl + 2);
                    }
                }
            }
        }
        __syncthreads();
        if (ch + 2 < NCH) load_stage(s, (ch + 2) * 32);
        CP_COMMIT();   // unconditional: keeps wait_group bookkeeping exact
    }

    // ---------------- epilogue -----------------------------------------------
#pragma unroll
    for (int mt = 0; mt < 4; mt++) {
        const int lm0 = wm * 64 + mt * 16 + r;       // local row of acc[0],acc[1]
        const int lm1 = lm0 + 8;                     // local row of acc[2],acc[3]
#pragma unroll
        for (int nt = 0; nt < 8; nt++) {
            const int bcol = n0 + wn * 64 + nt * 8 + c * 2;
            const float bb0 = bias[e * Nld + bcol];
            const float bb1 = bias[e * Nld + bcol + 1];
            if (GELU_EPI) {
                float v00 = gelu_f(acc[mt][nt][0] + bb0);
                float v01 = gelu_f(acc[mt][nt][1] + bb1);
                float v10 = gelu_f(acc[mt][nt][2] + bb0);
                float v11 = gelu_f(acc[mt][nt][3] + bb1);
                __nv_bfloat162 h0, h1, l0, l1;
                h0.x = __float2bfloat16_rn(v00);
                h0.y = __float2bfloat16_rn(v01);
                h1.x = __float2bfloat16_rn(v10);
                h1.y = __float2bfloat16_rn(v11);
                l0.x = __float2bfloat16_rn(v00 - __bfloat162float(h0.x));
                l0.y = __float2bfloat16_rn(v01 - __bfloat162float(h0.y));
                l1.x = __float2bfloat16_rn(v10 - __bfloat162float(h1.x));
                l1.y = __float2bfloat16_rn(v11 - __bfloat162float(h1.y));
                *(__nv_bfloat162*)(outbh + (size_t)(m0 + lm0) * Nld + bcol) = h0;
                *(__nv_bfloat162*)(outbh + (size_t)(m0 + lm1) * Nld + bcol) = h1;
                *(__nv_bfloat162*)(outbl + (size_t)(m0 + lm0) * Nld + bcol) = l0;
                *(__nv_bfloat162*)(outbl + (size_t)(m0 + lm1) * Nld + bcol) = l1;
            } else {
                const float w0 = val_s[lm0];
                const float w1 = val_s[lm1];
                float* p0 = outa + (size_t)tok_s[lm0] * ND + bcol;
                float* p1 = outa + (size_t)tok_s[lm1] * ND + bcol;
                red_v2(p0, (acc[mt][nt][0] + bb0) * w0, (acc[mt][nt][1] + bb1) * w0);
                red_v2(p1, (acc[mt][nt][2] + bb0) * w1, (acc[mt][nt][3] + bb1) * w1);
            }
        }
    }
}

// ============================ host launch =====================================
extern "C" void kernel_launch(void* const* d_in, const int* in_sizes, int n_in,
                              void* d_out, int out_size) {
    const float* x  = (const float*)d_in[0];   // [T, D]
    const float* Wg = (const float*)d_in[1];   // [D, E]
    const float* W1 = (const float*)d_in[2];   // [E, D, F]
    const float* b1 = (const float*)d_in[3];   // [E, F]
    const float* W2 = (const float*)d_in[4];   // [E, F, D]
    const float* b2 = (const float*)d_in[5];   // [E, D]
    float* out = (float*)d_out;

    void *p_xh, *p_xl, *p_w1h, *p_w1l, *p_w2h, *p_w2l, *p_hh, *p_hl;
    cudaGetSymbolAddress(&p_xh, g_xh);
    cudaGetSymbolAddress(&p_xl, g_xl);
    cudaGetSymbolAddress(&p_w1h, g_w1h);
    cudaGetSymbolAddress(&p_w1l, g_w1l);
    cudaGetSymbolAddress(&p_w2h, g_w2h);
    cudaGetSymbolAddress(&p_w2l, g_w2l);
    cudaGetSymbolAddress(&p_hh, g_hh);
    cudaGetSymbolAddress(&p_hl, g_hl);

    cudaFuncSetAttribute((const void*)gemm_tc_kernel<32, true, true>,
                         cudaFuncAttributeMaxDynamicSharedMemorySize,
                         GEMM_SMEM_BYTES);
    cudaFuncSetAttribute((const void*)gemm_tc_kernel<128, false, false>,
                         cudaFuncAttributeMaxDynamicSharedMemorySize,
                         GEMM_SMEM_BYTES);

    size_t n_main = (size_t)NT * ND;
    init_out_kernel<<<512, 256>>>(out, n_main, (size_t)out_size);
    router_kernel<<<NT / 32, 1024>>>(x, Wg);
    topk_kernel<<<NE, 1024>>>();

    // Pre-split operands into bf16 hi/lo planes.
    split_kernel<<<1024, 256>>>((const float4*)x,
                                (__nv_bfloat162*)p_xh, (__nv_bfloat162*)p_xl,
                                (size_t)NT * ND / 4);
    split_kernel<<<2048, 256>>>((const float4*)W1,
                                (__nv_bfloat162*)p_w1h, (__nv_bfloat162*)p_w1l,
                                (size_t)NE * ND * NF / 4);
    split_kernel<<<2048, 256>>>((const float4*)W2,
                                (__nv_bfloat162*)p_w2h, (__nv_bfloat162*)p_w2l,
                                (size_t)NE * NF * ND / 4);

    // GEMM1: h = gelu(x[idx] @ W1[e] + b1[e])   M=16384, N=4096, K=1024
    gemm_tc_kernel<32, true, true>
        <<<dim3(NF / 256, NM / 128), 256, GEMM_SMEM_BYTES>>>(
            (const __nv_bfloat16*)p_xh, (const __nv_bfloat16*)p_xl,
            (const __nv_bfloat16*)p_w1h, (const __nv_bfloat16*)p_w1l,
            b1, nullptr,
            (__nv_bfloat16*)p_hh, (__nv_bfloat16*)p_hl, NF);

    // GEMM2: out[tok] += val * (h @ W2[e] + b2[e])   M=16384, N=1024, K=4096
    gemm_tc_kernel<128, false, false>
        <<<dim3(ND / 256, NM / 128), 256, GEMM_SMEM_BYTES>>>(
            (const __nv_bfloat16*)p_hh, (const __nv_bfloat16*)p_hl,
            (const __nv_bfloat16*)p_w2h, (const __nv_bfloat16*)p_w2l,
            b2, out, nullptr, nullptr, ND);
}

// round 6
// speedup vs baseline: 2.6443x; 1.0422x over previous
#include <cuda_runtime.h>
#include <cuda_bf16.h>
#include <cstdint>

// Problem constants
#define NE 8
#define ND 1024
#define NF 4096
#define NT 8192
#define NC 2048
#define NM (NE * NC)   // 16384 rows through the expert FFN

// ---------------- scratch (device globals; no runtime allocation) ----------
__device__ float g_scoresT[NE * NT];              // gates^T  [E, T]
__device__ int   g_idx[NM];                       // selected token ids [E*C]
__device__ float g_vals[NM];                      // routing probs of selected
__device__ __nv_bfloat16 g_xh[(size_t)NT * ND];   // x split hi
__device__ __nv_bfloat16 g_xl[(size_t)NT * ND];   // x split lo
__device__ __nv_bfloat16 g_w1h[(size_t)NE * ND * NF];
__device__ __nv_bfloat16 g_w1l[(size_t)NE * ND * NF];
__device__ __nv_bfloat16 g_w2h[(size_t)NE * NF * ND];
__device__ __nv_bfloat16 g_w2l[(size_t)NE * NF * ND];
__device__ __nv_bfloat16 g_hh[(size_t)NM * NF];   // gelu output split hi
__device__ __nv_bfloat16 g_hl[(size_t)NM * NF];   // gelu output split lo

// ---------------- init output ------------------------------------------------
__global__ void init_out_kernel(float* out, size_t n_main, size_t total) {
    size_t i = (size_t)blockIdx.x * blockDim.x + threadIdx.x;
    size_t stride = (size_t)gridDim.x * blockDim.x;
    for (; i < total; i += stride) {
        if (i < n_main)       out[i] = 0.0f;
        else if (i == n_main) out[i] = 2.0f;   // aux_loss = E*(C/T)*1 = 2 analytically
        else                  out[i] = 0.0f;
    }
}

// ---------------- fp32 -> (hi, lo) bf16 split, 8 floats/thread/iter ---------
__global__ void split_kernel(const float4* __restrict__ in,
                             uint4* __restrict__ hi,
                             uint4* __restrict__ lo, size_t n8) {
    size_t i = (size_t)blockIdx.x * blockDim.x + threadIdx.x;
    size_t stride = (size_t)gridDim.x * blockDim.x;
    for (; i < n8; i += stride) {
        float4 a = in[2 * i];
        float4 b = in[2 * i + 1];
        __nv_bfloat162 h[4], l[4];
        h[0] = __floats2bfloat162_rn(a.x, a.y);
        h[1] = __floats2bfloat162_rn(a.z, a.w);
        h[2] = __floats2bfloat162_rn(b.x, b.y);
        h[3] = __floats2bfloat162_rn(b.z, b.w);
        l[0] = __floats2bfloat162_rn(a.x - __bfloat162float(h[0].x),
                                     a.y - __bfloat162float(h[0].y));
        l[1] = __floats2bfloat162_rn(a.z - __bfloat162float(h[1].x),
                                     a.w - __bfloat162float(h[1].y));
        l[2] = __floats2bfloat162_rn(b.x - __bfloat162float(h[2].x),
                                     b.y - __bfloat162float(h[2].y));
        l[3] = __floats2bfloat162_rn(b.z - __bfloat162float(h[3].x),
                                     b.w - __bfloat162float(h[3].y));
        hi[i] = *(const uint4*)h;
        lo[i] = *(const uint4*)l;
    }
}

// ---------------- router: gates = softmax(x @ Wg), stored transposed --------
__global__ void router_kernel(const float* __restrict__ x,
                              const float* __restrict__ Wg) {
    int warp = (blockIdx.x * blockDim.x + threadIdx.x) >> 5;
    int lane = threadIdx.x & 31;
    if (warp >= NT) return;
    const float* xr = x + (size_t)warp * ND;
    float acc[NE];
#pragma unroll
    for (int e = 0; e < NE; e++) acc[e] = 0.0f;
    for (int d = lane; d < ND; d += 32) {
        float xv = xr[d];
        const float4 w0 = *(const float4*)(Wg + d * NE);
        const float4 w1 = *(const float4*)(Wg + d * NE + 4);
        acc[0] += xv * w0.x; acc[1] += xv * w0.y;
        acc[2] += xv * w0.z; acc[3] += xv * w0.w;
        acc[4] += xv * w1.x; acc[5] += xv * w1.y;
        acc[6] += xv * w1.z; acc[7] += xv * w1.w;
    }
#pragma unroll
    for (int off = 16; off > 0; off >>= 1) {
#pragma unroll
        for (int e = 0; e < NE; e++)
            acc[e] += __shfl_down_sync(0xffffffffu, acc[e], off);
    }
    if (lane == 0) {
        float m = acc[0];
#pragma unroll
        for (int e = 1; e < NE; e++) m = fmaxf(m, acc[e]);
        float s = 0.0f;
#pragma unroll
        for (int e = 0; e < NE; e++) { acc[e] = expf(acc[e] - m); s += acc[e]; }
        float inv = 1.0f / s;
#pragma unroll
        for (int e = 0; e < NE; e++) g_scoresT[e * NT + warp] = acc[e] * inv;
    }
}

// ---------------- exact top-C per expert via 4-pass radix select ------------
__global__ void topk_kernel() {
    int e = blockIdx.x;
    int tid = threadIdx.x;
    const float* s = g_scoresT + e * NT;

    __shared__ unsigned hist[256];
    __shared__ unsigned sh_prefix;
    __shared__ int sh_rem;

    unsigned prefix = 0;
    int remaining = NC;

    for (int shift = 24; shift >= 0; shift -= 8) {
        if (tid < 256) hist[tid] = 0;
        __syncthreads();
        unsigned mask = (shift == 24) ? 0u : (0xFFFFFFFFu << (shift + 8));
        for (int t = tid; t < NT; t += blockDim.x) {
            unsigned k = __float_as_uint(s[t]);
            if ((k & mask) == prefix) atomicAdd(&hist[(k >> shift) & 0xFFu], 1u);
        }
        __syncthreads();
        if (tid == 0) {
            int rem = remaining;
            int b = 0;
            for (int d = 255; d >= 0; d--) {
                int h = (int)hist[d];
                if (h >= rem) { b = d; break; }
                rem -= h;
            }
            sh_prefix = prefix | ((unsigned)b << shift);
            sh_rem = rem;
        }
        __syncthreads();
        prefix = sh_prefix;
        remaining = sh_rem;
        __syncthreads();
    }

    __shared__ int cnt_gt, cnt_eq;
    if (tid == 0) { cnt_gt = 0; cnt_eq = 0; }
    __syncthreads();
    int base = NC - remaining;
    for (int t = tid; t < NT; t += blockDim.x) {
        unsigned k = __float_as_uint(s[t]);
        if (k > prefix) {
            int p = atomicAdd(&cnt_gt, 1);
            g_idx[e * NC + p]  = t;
            g_vals[e * NC + p] = s[t];
        } else if (k == prefix) {
            int p = atomicAdd(&cnt_eq, 1);
            if (p < remaining) {
                g_idx[e * NC + base + p]  = t;
                g_vals[e * NC + base + p] = s[t];
            }
        }
    }
}

// ---------------- gelu (tanh approx via fast exp; matches jax to ~1e-6) -----
__device__ __forceinline__ float gelu_f(float v) {
    float u = 0.7978845608028654f * (v + 0.044715f * v * v * v);
    float t = 1.0f - 2.0f / (__expf(2.0f * u) + 1.0f);
    return 0.5f * v * (1.0f + t);
}

// ============================ 3xBF16 mma.sync GEMM ============================
// CTA tile 128(M) x 256(N) x 32(K). 8 warps 2(m) x 4(n), warp tile 64x64.
// hi*hi + lo*hi + hi*lo on mma.m16n8k16.bf16, fp32 accum.
// 3-stage cp.async pipeline, one __syncthreads per chunk, precomputed ptrs.

static constexpr int A_STRIDE = 40;                 // bf16 units (80 B)
static constexpr int A_PLANE  = 128 * A_STRIDE;     // 5120
static constexpr int A_STAGE  = 2 * A_PLANE;        // hi + lo = 10240
static constexpr int B_BASE   = 3 * A_STAGE;        // 30720
static constexpr int B_STRIDE = 264;                // bf16 units (528 B)
static constexpr int B_PLANE  = 32 * B_STRIDE;      // 8448
static constexpr int B_STAGE  = 2 * B_PLANE;        // 16896
static constexpr int SMEM_BF16 = B_BASE + 3 * B_STAGE;       // 81408
static constexpr int GEMM_SMEM_BYTES = SMEM_BF16 * 2;        // 162816

__device__ __forceinline__ uint32_t smem_u32(const void* p) {
    uint32_t a;
    asm("{ .reg .u64 t; cvta.to.shared.u64 t, %1; cvt.u32.u64 %0, t; }"
        : "=r"(a) : "l"(p));
    return a;
}

__device__ __forceinline__ void cp16(uint32_t dst, const void* src) {
    asm volatile("cp.async.cg.shared.global [%0], [%1], 16;"
                 :: "r"(dst), "l"(src) : "memory");
}
#define CP_COMMIT() asm volatile("cp.async.commit_group;" ::: "memory")
#define CP_WAIT1()  asm volatile("cp.async.wait_group 1;" ::: "memory")

__device__ __forceinline__ void ldsm4(uint32_t* r, uint32_t addr) {
    asm volatile("ldmatrix.sync.aligned.m8n8.x4.shared.b16 {%0,%1,%2,%3}, [%4];"
                 : "=r"(r[0]), "=r"(r[1]), "=r"(r[2]), "=r"(r[3]) : "r"(addr));
}
__device__ __forceinline__ void ldsm4t(uint32_t* r, uint32_t addr) {
    asm volatile("ldmatrix.sync.aligned.m8n8.x4.trans.shared.b16 {%0,%1,%2,%3}, [%4];"
                 : "=r"(r[0]), "=r"(r[1]), "=r"(r[2]), "=r"(r[3]) : "r"(addr));
}

__device__ __forceinline__ void mma_bf16(float* d, const uint32_t* a,
                                         const uint32_t* b) {
    asm volatile(
        "mma.sync.aligned.m16n8k16.row.col.f32.bf16.bf16.f32 "
        "{%0,%1,%2,%3}, {%4,%5,%6,%7}, {%8,%9}, {%0,%1,%2,%3};"
        : "+f"(d[0]), "+f"(d[1]), "+f"(d[2]), "+f"(d[3])
        : "r"(a[0]), "r"(a[1]), "r"(a[2]), "r"(a[3]), "r"(b[0]), "r"(b[1]));
}

__device__ __forceinline__ void red_v2(float* ptr, float v0, float v1) {
    asm volatile("red.global.add.v2.f32 [%0], {%1, %2};"
                 :: "l"(ptr), "f"(v0), "f"(v1) : "memory");
}

// NCH chunks of K=32 per CTA (per K-slice). GATHER: A rows via g_idx (lda=ND).
// GELU_EPI: write split-bf16 gelu(acc+bias); else scatter-add (acc+bias?)*val.
// blockIdx.z = K-slice; slice 0 adds bias. Ktot = full K (B expert stride).
template<int NCH, bool GATHER, bool GELU_EPI>
__global__ __launch_bounds__(256) void gemm_tc_kernel(
    const __nv_bfloat16* __restrict__ Ah,
    const __nv_bfloat16* __restrict__ Al,
    const __nv_bfloat16* __restrict__ Bh,
    const __nv_bfloat16* __restrict__ Bl,
    const float* __restrict__ bias,
    float* __restrict__ outa,
    __nv_bfloat16* __restrict__ outbh,
    __nv_bfloat16* __restrict__ outbl,
    int Nld, int lda, int Ktot) {
    extern __shared__ __align__(16) __nv_bfloat16 sm[];
    __shared__ int   tok_s[128];
    __shared__ float val_s[128];

    const int tid = threadIdx.x;
    const int warp = tid >> 5;
    const int lane = tid & 31;
    const int wm = warp >> 2;          // 0..1
    const int wn = warp & 3;           // 0..3
    const int r = lane >> 2;           // 0..7 (accumulator row)
    const int c = lane & 3;            // 0..3 (accumulator col pair)
    const int quad = lane >> 3;        // 0..3 (ldmatrix matrix id)
    const int r8 = lane & 7;           // row within 8x8 matrix

    const int n0 = blockIdx.x * 256;
    const int m0 = blockIdx.y * 128;
    const int e = m0 >> 11;            // m0 / NC
    const int kbase = blockIdx.z * NCH * 32;
    const bool bias_en = (blockIdx.z == 0);

    if (tid < 128) {
        tok_s[tid] = g_idx[m0 + tid];
        val_s[tid] = g_vals[m0 + tid];
    }
    __syncthreads();

    const uint32_t sbase = smem_u32(sm);

    // ---- precomputed load pointers (advance by one K-chunk per call) -------
    const __nv_bfloat16* asrc[4];
    uint32_t adst0[4];
    const __nv_bfloat16* bsrc[8];
    uint32_t bdst0[8];
    {
        const __nv_bfloat16* aps[2] = {Ah, Al};
        const size_t bexp = (size_t)e * Ktot * Nld + n0;
        const __nv_bfloat16* bps[2] = {Bh + bexp, Bl + bexp};
#pragma unroll
        for (int p = 0; p < 2; p++) {
#pragma unroll
            for (int i = 0; i < 2; i++) {
                int lin = tid + 256 * i;
                int row = lin >> 2;
                int seg = (lin & 3) * 8;
                int j = p * 2 + i;
                asrc[j] = GATHER
                    ? (aps[p] + (size_t)tok_s[row] * lda + kbase + seg)
                    : (aps[p] + (size_t)(m0 + row) * lda + kbase + seg);
                adst0[j] = sbase + (uint32_t)(p * A_PLANE + row * A_STRIDE + seg) * 2;
            }
#pragma unroll
            for (int i = 0; i < 4; i++) {
                int lin = tid + 256 * i;
                int row = lin >> 5;
                int seg = (lin & 31) * 8;
                int j = p * 4 + i;
                bsrc[j] = bps[p] + (size_t)(kbase + row) * Nld + seg;
                bdst0[j] = sbase + (uint32_t)(B_BASE + p * B_PLANE +
                                              row * B_STRIDE + seg) * 2;
            }
        }
    }

    auto load_stage = [&](int s) {
        const uint32_t ao = (uint32_t)s * (A_STAGE * 2);
        const uint32_t bo = (uint32_t)s * (B_STAGE * 2);
#pragma unroll
        for (int j = 0; j < 4; j++) {
            cp16(adst0[j] + ao, asrc[j]);
            asrc[j] += 32;
        }
#pragma unroll
        for (int j = 0; j < 8; j++) {
            cp16(bdst0[j] + bo, bsrc[j]);
            bsrc[j] += (size_t)32 * Nld;
        }
    };

    float acc[4][8][4];
#pragma unroll
    for (int mt = 0; mt < 4; mt++)
#pragma unroll
        for (int nt = 0; nt < 8; nt++)
#pragma unroll
            for (int i = 0; i < 4; i++) acc[mt][nt][i] = 0.0f;

    // prologue: fill stages 0, 1
    load_stage(0);
    CP_COMMIT();
    load_stage(1);
    CP_COMMIT();

#pragma unroll 1
    for (int ch = 0; ch < NCH; ch++) {
        const int s = ch % 3;
        CP_WAIT1();
        __syncthreads();
        if (ch + 2 < NCH) load_stage((ch + 2) % 3);
        CP_COMMIT();   // unconditional: keeps wait_group bookkeeping exact

        const uint32_t sa = sbase + (uint32_t)s * (A_STAGE * 2);
        const uint32_t sb = sbase + (uint32_t)(B_BASE * 2 + s * (B_STAGE * 2));
#pragma unroll
        for (int ks = 0; ks < 2; ks++) {
            // ---- A fragments: hi/lo x 4 m-tiles via ldmatrix.x4 ----
            uint32_t ah[4][4], al[4][4];
            {
                const int m_local = wm * 64 + (quad & 1) * 8 + r8;
                const int k_off = ks * 16 + (quad >> 1) * 8;
                const uint32_t abase = sa +
                    (uint32_t)(m_local * A_STRIDE + k_off) * 2;
#pragma unroll
                for (int mt = 0; mt < 4; mt++) {
                    ldsm4(ah[mt], abase + (uint32_t)(mt * 16 * A_STRIDE) * 2);
                    ldsm4(al[mt], abase + (uint32_t)(A_PLANE + mt * 16 * A_STRIDE) * 2);
                }
            }
            // ---- B fragments per 16-col group, then MMAs ----
            {
                const int k_row = ks * 16 + (quad & 1) * 8 + r8;
                const int n_col = wn * 64 + (quad >> 1) * 8;
                const uint32_t bbase = sb +
                    (uint32_t)(k_row * B_STRIDE + n_col) * 2;
#pragma unroll
                for (int nt2 = 0; nt2 < 4; nt2++) {
                    uint32_t bh[4], bl[4];
                    ldsm4t(bh, bbase + (uint32_t)(nt2 * 16) * 2);
                    ldsm4t(bl, bbase + (uint32_t)(B_PLANE + nt2 * 16) * 2);
                    const int nt = nt2 * 2;
#pragma unroll
                    for (int mt = 0; mt < 4; mt++) {
                        mma_bf16(acc[mt][nt],     ah[mt], bh);        // hi*hi
                        mma_bf16(acc[mt][nt],     al[mt], bh);        // lo*hi
                        mma_bf16(acc[mt][nt],     ah[mt], bl);        // hi*lo
                        mma_bf16(acc[mt][nt + 1], ah[mt], bh + 2);
                        mma_bf16(acc[mt][nt + 1], al[mt], bh + 2);
                        mma_bf16(acc[mt][nt + 1], ah[mt], bl + 2);
                    }
                }
            }
        }
        __syncthreads();
    }

    // ---------------- epilogue -----------------------------------------------
#pragma unroll
    for (int mt = 0; mt < 4; mt++) {
        const int lm0 = wm * 64 + mt * 16 + r;       // local row of acc[0],acc[1]
        const int lm1 = lm0 + 8;                     // local row of acc[2],acc[3]
#pragma unroll
        for (int nt = 0; nt < 8; nt++) {
            const int bcol = n0 + wn * 64 + nt * 8 + c * 2;
            const float bb0 = bias_en ? bias[e * Nld + bcol] : 0.0f;
            const float bb1 = bias_en ? bias[e * Nld + bcol + 1] : 0.0f;
            if (GELU_EPI) {
                float v00 = gelu_f(acc[mt][nt][0] + bb0);
                float v01 = gelu_f(acc[mt][nt][1] + bb1);
                float v10 = gelu_f(acc[mt][nt][2] + bb0);
                float v11 = gelu_f(acc[mt][nt][3] + bb1);
                __nv_bfloat162 h0, h1, l0, l1;
                h0.x = __float2bfloat16_rn(v00);
                h0.y = __float2bfloat16_rn(v01);
                h1.x = __float2bfloat16_rn(v10);
                h1.y = __float2bfloat16_rn(v11);
                l0.x = __float2bfloat16_rn(v00 - __bfloat162float(h0.x));
                l0.y = __float2bfloat16_rn(v01 - __bfloat162float(h0.y));
                l1.x = __float2bfloat16_rn(v10 - __bfloat162float(h1.x));
                l1.y = __float2bfloat16_rn(v11 - __bfloat162float(h1.y));
                *(__nv_bfloat162*)(outbh + (size_t)(m0 + lm0) * Nld + bcol) = h0;
                *(__nv_bfloat162*)(outbh + (size_t)(m0 + lm1) * Nld + bcol) = h1;
                *(__nv_bfloat162*)(outbl + (size_t)(m0 + lm0) * Nld + bcol) = l0;
                *(__nv_bfloat162*)(outbl + (size_t)(m0 + lm1) * Nld + bcol) = l1;
            } else {
                const float w0 = val_s[lm0];
                const float w1 = val_s[lm1];
                float* p0 = outa + (size_t)tok_s[lm0] * ND + bcol;
                float* p1 = outa + (size_t)tok_s[lm1] * ND + bcol;
                red_v2(p0, (acc[mt][nt][0] + bb0) * w0, (acc[mt][nt][1] + bb1) * w0);
                red_v2(p1, (acc[mt][nt][2] + bb0) * w1, (acc[mt][nt][3] + bb1) * w1);
            }
        }
    }
}

// ============================ host launch =====================================
extern "C" void kernel_launch(void* const* d_in, const int* in_sizes, int n_in,
                              void* d_out, int out_size) {
    const float* x  = (const float*)d_in[0];   // [T, D]
    const float* Wg = (const float*)d_in[1];   // [D, E]
    const float* W1 = (const float*)d_in[2];   // [E, D, F]
    const float* b1 = (const float*)d_in[3];   // [E, F]
    const float* W2 = (const float*)d_in[4];   // [E, F, D]
    const float* b2 = (const float*)d_in[5];   // [E, D]
    float* out = (float*)d_out;

    void *p_xh, *p_xl, *p_w1h, *p_w1l, *p_w2h, *p_w2l, *p_hh, *p_hl;
    cudaGetSymbolAddress(&p_xh, g_xh);
    cudaGetSymbolAddress(&p_xl, g_xl);
    cudaGetSymbolAddress(&p_w1h, g_w1h);
    cudaGetSymbolAddress(&p_w1l, g_w1l);
    cudaGetSymbolAddress(&p_w2h, g_w2h);
    cudaGetSymbolAddress(&p_w2l, g_w2l);
    cudaGetSymbolAddress(&p_hh, g_hh);
    cudaGetSymbolAddress(&p_hl, g_hl);

    cudaFuncSetAttribute((const void*)gemm_tc_kernel<32, true, true>,
                         cudaFuncAttributeMaxDynamicSharedMemorySize,
                         GEMM_SMEM_BYTES);
    cudaFuncSetAttribute((const void*)gemm_tc_kernel<64, false, false>,
                         cudaFuncAttributeMaxDynamicSharedMemorySize,
                         GEMM_SMEM_BYTES);

    size_t n_main = (size_t)NT * ND;
    init_out_kernel<<<512, 256>>>(out, n_main, (size_t)out_size);
    router_kernel<<<NT / 32, 1024>>>(x, Wg);
    topk_kernel<<<NE, 1024>>>();

    // Pre-split operands into bf16 hi/lo planes (8 floats per thread-iter).
    split_kernel<<<1024, 256>>>((const float4*)x,
                                (uint4*)p_xh, (uint4*)p_xl,
                                (size_t)NT * ND / 8);
    split_kernel<<<4096, 256>>>((const float4*)W1,
                                (uint4*)p_w1h, (uint4*)p_w1l,
                                (size_t)NE * ND * NF / 8);
    split_kernel<<<4096, 256>>>((const float4*)W2,
                                (uint4*)p_w2h, (uint4*)p_w2l,
                                (size_t)NE * NF * ND / 8);

    // GEMM1: h = gelu(x[idx] @ W1[e] + b1[e])   M=16384, N=4096, K=1024
    gemm_tc_kernel<32, true, true>
        <<<dim3(NF / 256, NM / 128, 1), 256, GEMM_SMEM_BYTES>>>(
            (const __nv_bfloat16*)p_xh, (const __nv_bfloat16*)p_xl,
            (const __nv_bfloat16*)p_w1h, (const __nv_bfloat16*)p_w1l,
            b1, nullptr,
            (__nv_bfloat16*)p_hh, (__nv_bfloat16*)p_hl, NF, ND, ND);

    // GEMM2: out[tok] += val*(h @ W2[e] + b2[e])  M=16384, N=1024, K=4096
    // split-K = 2 (epilogue is scatter-add, so K-slices just both reduce in)
    gemm_tc_kernel<64, false, false>
        <<<dim3(ND / 256, NM / 128, 2), 256, GEMM_SMEM_BYTES>>>(
            (const __nv_bfloat16*)p_hh, (const __nv_bfloat16*)p_hl,
            (const __nv_bfloat16*)p_w2h, (const __nv_bfloat16*)p_w2l,
            b2, out, nullptr, nullptr, ND, NF, NF);
}